// round 13
// baseline (speedup 1.0000x reference)
#include <cuda_runtime.h>

// TensorNeRF compositing: globally-compacted two-phase, self-cleaning.
//  K1 (thread-per-ray): slab test; misses write outputs; hits append packed
//      (ray params + window) to a global queue.
//  K2 (warp-per-hit-ray): latency-flattened composite:
//      (a) prefetch ALL (<=8) sigma chunk loads in parallel,
//      (b) compute all chunk scans with ILP (scans are independent; only the
//          tiny runT weave is sequential),
//      (c) issue all rgb loads in parallel, then accumulate.
// Geometry bound: t_exit <= (1.5+|o|)/max|d_i| <= ~3.4 => window <= ~180
// samples <= 8 chunks (serial fallback kept for safety).
// Out-of-bbox samples have cumprod factor (1-0+1e-10)==1.0f exactly in f32.

#define S_SAMPLES 512
#define MAX_RAYS 32768
#define PHASEB_BLOCKS 592
#define MAXCH 8

__device__ int g_cnt  = 0;
__device__ int g_done = 0;
__device__ float4 g_qo[MAX_RAYS];   // ox, oy, oz, bitcast(ray)
__device__ float4 g_qd[MAX_RAYS];   // dx, dy, dz, bitcast(c0 | c1<<16)

__global__ __launch_bounds__(128) void phaseA_kernel(
    const float* __restrict__ rays_o,
    const float* __restrict__ rays_d,
    const float* __restrict__ aabb,
    float* __restrict__ out,
    int N)
{
    const int ray = blockIdx.x * blockDim.x + threadIdx.x;
    if (ray >= N) return;

    const float ax0 = aabb[0], ay0 = aabb[1], az0 = aabb[2];
    const float ax1 = aabb[3], ay1 = aabb[4], az1 = aabb[5];
    const float NEAR = 2.0f, FAR = 6.0f;
    const float step = 4.0f / 511.0f;

    const float ox = rays_o[ray * 3 + 0];
    const float oy = rays_o[ray * 3 + 1];
    const float oz = rays_o[ray * 3 + 2];
    const float dx = rays_d[ray * 3 + 0];
    const float dy = rays_d[ray * 3 + 1];
    const float dz = rays_d[ray * 3 + 2];

    const float idx_ = __frcp_rn(dx);
    const float idy_ = __frcp_rn(dy);
    const float idz_ = __frcp_rn(dz);
    const float txa = (ax0 - ox) * idx_, txb = (ax1 - ox) * idx_;
    const float tya = (ay0 - oy) * idy_, tyb = (ay1 - oy) * idy_;
    const float tza = (az0 - oz) * idz_, tzb = (az1 - oz) * idz_;
    float t_ent = fmaxf(fmaxf(fminf(txa, txb), fminf(tya, tyb)), fminf(tza, tzb));
    float t_exi = fminf(fminf(fmaxf(txa, txb), fmaxf(tya, tyb)), fmaxf(tza, tzb));
    t_ent = fmaxf(t_ent, NEAR);
    t_exi = fminf(t_exi, FAR);

    bool miss = (t_ent > t_exi + 2.0f * step);
    int c0 = 0, c1 = -1;
    if (!miss) {
        int s_lo = __float2int_rd((t_ent - NEAR) * (511.0f / 4.0f)) - 2;
        int s_hi = __float2int_ru((t_exi - NEAR) * (511.0f / 4.0f)) + 2;
        s_lo = max(s_lo, 0);
        s_hi = min(s_hi, S_SAMPLES - 1);
        if (s_lo > s_hi) miss = true;
        else { c0 = s_lo >> 5; c1 = s_hi >> 5; }
    }

    if (miss) {
        out[ray * 3 + 0] = 0.0f;
        out[ray * 3 + 1] = 0.0f;
        out[ray * 3 + 2] = 0.0f;
        out[3 * N + ray] = 0.0f;
        out[4 * N + ray] = 1.0f;
    } else {
        const int h = atomicAdd(&g_cnt, 1);
        g_qo[h] = make_float4(ox, oy, oz, __int_as_float(ray));
        g_qd[h] = make_float4(dx, dy, dz, __int_as_float(c0 | (c1 << 16)));
    }
}

__global__ __launch_bounds__(256) void phaseB_kernel(
    const float* __restrict__ sigma_feat,
    const float* __restrict__ rgb,
    const float* __restrict__ aabb,
    float* __restrict__ out,
    int N)
{
    const int lane  = threadIdx.x & 31;
    const int gwarp = (blockIdx.x * blockDim.x + threadIdx.x) >> 5;
    const int nwarp = (gridDim.x * blockDim.x) >> 5;
    const int nh = g_cnt;

    const float ax0 = aabb[0], ay0 = aabb[1], az0 = aabb[2];
    const float ax1 = aabb[3], ay1 = aabb[4], az1 = aabb[5];
    const float NEAR = 2.0f;
    const float DENSITY_SHIFT = -10.0f;
    const float step = 4.0f / 511.0f;
    const float dist = step * 25.0f;

    for (int h = gwarp; h < nh; h += nwarp) {
        const float4 qo = g_qo[h];
        const float4 qd = g_qd[h];
        const int r   = __float_as_int(qo.w);
        const int win = __float_as_int(qd.w);
        const int c0  = win & 0xffff;
        const int c1  = win >> 16;
        const int nch = c1 - c0 + 1;
        const float ox = qo.x, oy = qo.y, oz = qo.z;
        const float dx = qd.x, dy = qd.y, dz = qd.z;

        const float* __restrict__ sf = sigma_feat + (size_t)r * S_SAMPLES;
        const float* __restrict__ rg = rgb + (size_t)r * S_SAMPLES * 3;

        // (a) prefetch all sigma chunk loads (independent, clamped)
        float sig[MAXCH];
        #pragma unroll
        for (int j = 0; j < MAXCH; ++j) {
            const int cc = min(c0 + j, (S_SAMPLES / 32) - 1);
            sig[j] = sf[cc * 32 + lane];
        }

        // (b) per-chunk alpha/factor + independent warp scans (ILP)
        float alpha[MAXCH], incl[MAXCH], excl[MAXCH];
        #pragma unroll
        for (int j = 0; j < MAXCH; ++j) {
            if (j < nch) {
                const int s = (c0 + j) * 32 + lane;
                const float t = fmaf(step, (float)s, NEAR);
                const float px = fmaf(dx, t, ox);
                const float py = fmaf(dy, t, oy);
                const float pz = fmaf(dz, t, oz);
                const bool inb = (px >= ax0) & (px <= ax1) &
                                 (py >= ay0) & (py <= ay1) &
                                 (pz >= az0) & (pz <= az1);
                const float x = sig[j] + DENSITY_SHIFT;
                float sp = (x > 20.0f) ? x : __logf(1.0f + __expf(x));
                const float sigma = inb ? sp : 0.0f;
                const float e = __expf(-sigma * dist);
                alpha[j] = 1.0f - e;
                float ic = e + 1e-10f;
                #pragma unroll
                for (int off = 1; off < 32; off <<= 1) {
                    const float v = __shfl_up_sync(0xffffffffu, ic, off);
                    if (lane >= off) ic *= v;
                }
                incl[j] = ic;
                float ex = __shfl_up_sync(0xffffffffu, ic, 1);
                excl[j] = (lane == 0) ? 1.0f : ex;
            }
        }

        // runT weave (cheap sequential part) -> per-chunk weights
        float runT = 1.0f;
        float w[MAXCH];
        #pragma unroll
        for (int j = 0; j < MAXCH; ++j) {
            if (j < nch) {
                w[j] = alpha[j] * runT * excl[j];
                runT *= __shfl_sync(0xffffffffu, incl[j], 31);
            }
        }

        // (c) all rgb loads issue together; accumulate
        float racc = 0.0f, gacc = 0.0f, bacc = 0.0f, dacc = 0.0f;
        #pragma unroll
        for (int j = 0; j < MAXCH; ++j) {
            if (j < nch) {
                const int s = (c0 + j) * 32 + lane;
                const float t = fmaf(step, (float)s, NEAR);
                racc += w[j] * rg[s * 3 + 0];
                gacc += w[j] * rg[s * 3 + 1];
                bacc += w[j] * rg[s * 3 + 2];
                dacc += w[j] * t;
            }
        }

        // serial fallback for windows wider than MAXCH chunks (not expected)
        #pragma unroll 1
        for (int c = c0 + MAXCH; c <= c1; ++c) {
            const int s = c * 32 + lane;
            const float t = fmaf(step, (float)s, NEAR);
            const float px = fmaf(dx, t, ox);
            const float py = fmaf(dy, t, oy);
            const float pz = fmaf(dz, t, oz);
            const bool inb = (px >= ax0) & (px <= ax1) &
                             (py >= ay0) & (py <= ay1) &
                             (pz >= az0) & (pz <= az1);
            const float x = sf[s] + DENSITY_SHIFT;
            float sp = (x > 20.0f) ? x : __logf(1.0f + __expf(x));
            const float sigma = inb ? sp : 0.0f;
            const float e = __expf(-sigma * dist);
            const float a = 1.0f - e;
            float ic = e + 1e-10f;
            #pragma unroll
            for (int off = 1; off < 32; off <<= 1) {
                const float v = __shfl_up_sync(0xffffffffu, ic, off);
                if (lane >= off) ic *= v;
            }
            float ex = __shfl_up_sync(0xffffffffu, ic, 1);
            if (lane == 0) ex = 1.0f;
            const float ww = a * runT * ex;
            racc += ww * rg[s * 3 + 0];
            gacc += ww * rg[s * 3 + 1];
            bacc += ww * rg[s * 3 + 2];
            dacc += ww * t;
            runT *= __shfl_sync(0xffffffffu, ic, 31);
        }

        #pragma unroll
        for (int off = 16; off; off >>= 1) {
            racc += __shfl_down_sync(0xffffffffu, racc, off);
            gacc += __shfl_down_sync(0xffffffffu, gacc, off);
            bacc += __shfl_down_sync(0xffffffffu, bacc, off);
            dacc += __shfl_down_sync(0xffffffffu, dacc, off);
        }

        if (lane == 0) {
            out[r * 3 + 0] = racc;
            out[r * 3 + 1] = gacc;
            out[r * 3 + 2] = bacc;
            out[3 * N + r] = dacc;
            out[4 * N + r] = runT;
        }
    }

    // Self-clean: last block resets counters for the next replay.
    __syncthreads();
    if (threadIdx.x == 0) {
        __threadfence();
        const int done = atomicAdd(&g_done, 1);
        if (done == gridDim.x - 1) {
            g_cnt  = 0;
            g_done = 0;
            __threadfence();
        }
    }
}

extern "C" void kernel_launch(void* const* d_in, const int* in_sizes, int n_in,
                              void* d_out, int out_size) {
    const float* rays_o     = (const float*)d_in[0];
    const float* rays_d     = (const float*)d_in[1];
    const float* sigma_feat = (const float*)d_in[2];
    const float* rgb        = (const float*)d_in[3];
    const float* aabb       = (const float*)d_in[4];
    float* out = (float*)d_out;

    const int N = in_sizes[0] / 3;

    phaseA_kernel<<<(N + 127) / 128, 128>>>(rays_o, rays_d, aabb, out, N);
    phaseB_kernel<<<PHASEB_BLOCKS, 256>>>(sigma_feat, rgb, aabb, out, N);
}

// round 14
// speedup vs baseline: 1.4236x; 1.4236x over previous
#include <cuda_runtime.h>

// TensorNeRF compositing: globally-compacted two-phase, self-cleaning.
//  K1 (thread-per-ray): slab test; misses write outputs; hits append packed
//      (ray params + window) to a global queue -> phaseB needs ONE load round.
//  K2 (warp-per-hit-ray, grid-stride, 888 blocks = 6/SM at 40 regs): 32-sample
//      chunks, exact per-sample predicate, warp-scan cumprod. Last block
//      resets counters for the next replay.
// Out-of-bbox samples have cumprod factor (1-0+1e-10)==1.0f exactly in f32,
// so restricting to the conservative window is exact.
// R13 lesson: full per-ray flattening costs regs (75) + wasted prefetch
// traffic; latency is better hidden by MORE WARPS (R9/R10 scaling evidence).

#define S_SAMPLES 512
#define MAX_RAYS 32768
#define PHASEB_BLOCKS 888

__device__ int g_cnt  = 0;
__device__ int g_done = 0;
__device__ float4 g_qo[MAX_RAYS];   // ox, oy, oz, bitcast(ray)
__device__ float4 g_qd[MAX_RAYS];   // dx, dy, dz, bitcast(c0 | c1<<16)

__global__ __launch_bounds__(128) void phaseA_kernel(
    const float* __restrict__ rays_o,
    const float* __restrict__ rays_d,
    const float* __restrict__ aabb,
    float* __restrict__ out,
    int N)
{
    const int ray = blockIdx.x * blockDim.x + threadIdx.x;
    if (ray >= N) return;

    const float ax0 = aabb[0], ay0 = aabb[1], az0 = aabb[2];
    const float ax1 = aabb[3], ay1 = aabb[4], az1 = aabb[5];
    const float NEAR = 2.0f, FAR = 6.0f;
    const float step = 4.0f / 511.0f;

    const float ox = rays_o[ray * 3 + 0];
    const float oy = rays_o[ray * 3 + 1];
    const float oz = rays_o[ray * 3 + 2];
    const float dx = rays_d[ray * 3 + 0];
    const float dy = rays_d[ray * 3 + 1];
    const float dz = rays_d[ray * 3 + 2];

    const float idx_ = __frcp_rn(dx);
    const float idy_ = __frcp_rn(dy);
    const float idz_ = __frcp_rn(dz);
    const float txa = (ax0 - ox) * idx_, txb = (ax1 - ox) * idx_;
    const float tya = (ay0 - oy) * idy_, tyb = (ay1 - oy) * idy_;
    const float tza = (az0 - oz) * idz_, tzb = (az1 - oz) * idz_;
    float t_ent = fmaxf(fmaxf(fminf(txa, txb), fminf(tya, tyb)), fminf(tza, tzb));
    float t_exi = fminf(fminf(fmaxf(txa, txb), fmaxf(tya, tyb)), fmaxf(tza, tzb));
    t_ent = fmaxf(t_ent, NEAR);
    t_exi = fminf(t_exi, FAR);

    bool miss = (t_ent > t_exi + 2.0f * step);
    int c0 = 0, c1 = -1;
    if (!miss) {
        int s_lo = __float2int_rd((t_ent - NEAR) * (511.0f / 4.0f)) - 2;
        int s_hi = __float2int_ru((t_exi - NEAR) * (511.0f / 4.0f)) + 2;
        s_lo = max(s_lo, 0);
        s_hi = min(s_hi, S_SAMPLES - 1);
        if (s_lo > s_hi) miss = true;
        else { c0 = s_lo >> 5; c1 = s_hi >> 5; }
    }

    if (miss) {
        out[ray * 3 + 0] = 0.0f;
        out[ray * 3 + 1] = 0.0f;
        out[ray * 3 + 2] = 0.0f;
        out[3 * N + ray] = 0.0f;
        out[4 * N + ray] = 1.0f;
    } else {
        const int h = atomicAdd(&g_cnt, 1);
        g_qo[h] = make_float4(ox, oy, oz, __int_as_float(ray));
        g_qd[h] = make_float4(dx, dy, dz, __int_as_float(c0 | (c1 << 16)));
    }
}

__global__ __launch_bounds__(256) void phaseB_kernel(
    const float* __restrict__ sigma_feat,
    const float* __restrict__ rgb,
    const float* __restrict__ aabb,
    float* __restrict__ out,
    int N)
{
    const int lane  = threadIdx.x & 31;
    const int gwarp = (blockIdx.x * blockDim.x + threadIdx.x) >> 5;
    const int nwarp = (gridDim.x * blockDim.x) >> 5;
    const int nh = g_cnt;

    const float ax0 = aabb[0], ay0 = aabb[1], az0 = aabb[2];
    const float ax1 = aabb[3], ay1 = aabb[4], az1 = aabb[5];
    const float NEAR = 2.0f;
    const float DENSITY_SHIFT = -10.0f;
    const float step = 4.0f / 511.0f;
    const float dist = step * 25.0f;

    for (int h = gwarp; h < nh; h += nwarp) {
        const float4 qo = g_qo[h];
        const float4 qd = g_qd[h];
        const int r   = __float_as_int(qo.w);
        const int win = __float_as_int(qd.w);
        const int c0  = win & 0xffff;
        const int c1  = win >> 16;
        const float ox = qo.x, oy = qo.y, oz = qo.z;
        const float dx = qd.x, dy = qd.y, dz = qd.z;

        const float* __restrict__ sf = sigma_feat + (size_t)r * S_SAMPLES;
        const float* __restrict__ rg = rgb + (size_t)r * S_SAMPLES * 3;

        float runT = 1.0f;
        float racc = 0.0f, gacc = 0.0f, bacc = 0.0f, dacc = 0.0f;

        #pragma unroll 1
        for (int c = c0; c <= c1; ++c) {
            const int s = c * 32 + lane;
            const float t = fmaf(step, (float)s, NEAR);
            const float px = fmaf(dx, t, ox);
            const float py = fmaf(dy, t, oy);
            const float pz = fmaf(dz, t, oz);
            const bool inb = (px >= ax0) & (px <= ax1) &
                             (py >= ay0) & (py <= ay1) &
                             (pz >= az0) & (pz <= az1);

            const float x = sf[s] + DENSITY_SHIFT;
            float sp = (x > 20.0f) ? x : __logf(1.0f + __expf(x));
            const float sigma = inb ? sp : 0.0f;

            const float e = __expf(-sigma * dist);
            const float alpha = 1.0f - e;
            const float f = e + 1e-10f;

            float incl = f;
            #pragma unroll
            for (int off = 1; off < 32; off <<= 1) {
                const float v = __shfl_up_sync(0xffffffffu, incl, off);
                if (lane >= off) incl *= v;
            }
            float excl = __shfl_up_sync(0xffffffffu, incl, 1);
            if (lane == 0) excl = 1.0f;

            const float w = alpha * runT * excl;

            racc += w * rg[s * 3 + 0];
            gacc += w * rg[s * 3 + 1];
            bacc += w * rg[s * 3 + 2];
            dacc += w * t;

            runT *= __shfl_sync(0xffffffffu, incl, 31);
        }

        #pragma unroll
        for (int off = 16; off; off >>= 1) {
            racc += __shfl_down_sync(0xffffffffu, racc, off);
            gacc += __shfl_down_sync(0xffffffffu, gacc, off);
            bacc += __shfl_down_sync(0xffffffffu, bacc, off);
            dacc += __shfl_down_sync(0xffffffffu, dacc, off);
        }

        if (lane == 0) {
            out[r * 3 + 0] = racc;
            out[r * 3 + 1] = gacc;
            out[r * 3 + 2] = bacc;
            out[3 * N + r] = dacc;
            out[4 * N + r] = runT;
        }
    }

    // Self-clean: last block resets counters for the next replay.
    __syncthreads();
    if (threadIdx.x == 0) {
        __threadfence();
        const int done = atomicAdd(&g_done, 1);
        if (done == gridDim.x - 1) {
            g_cnt  = 0;
            g_done = 0;
            __threadfence();
        }
    }
}

extern "C" void kernel_launch(void* const* d_in, const int* in_sizes, int n_in,
                              void* d_out, int out_size) {
    const float* rays_o     = (const float*)d_in[0];
    const float* rays_d     = (const float*)d_in[1];
    const float* sigma_feat = (const float*)d_in[2];
    const float* rgb        = (const float*)d_in[3];
    const float* aabb       = (const float*)d_in[4];
    float* out = (float*)d_out;

    const int N = in_sizes[0] / 3;

    phaseA_kernel<<<(N + 127) / 128, 128>>>(rays_o, rays_d, aabb, out, N);
    phaseB_kernel<<<PHASEB_BLOCKS, 256>>>(sigma_feat, rgb, aabb, out, N);
}